// round 14
// baseline (speedup 1.0000x reference)
#include <cuda_runtime.h>
#include <cstdint>

// ---------------- problem constants ----------------
#define G_    64
#define T_    8192
#define DIN_  2560
#define DOUT_ 1664
#define CAP_  256

// ---------------- tiling ----------------
#define BM 64
#define BN 256
#define BK 16
#define NK (DIN_ / BK)                 // 160
#define NT_N ((DOUT_ + BN - 1) / BN)   // 7 (last tile masked)

// fp16 smem ring (NO raw f32 staging)
#define LDA_B 48                       // A fp16 row stride (32 data + 16 pad)
#define LDB_B 528                      // B fp16 row stride (512 data + 16 pad)
#define FP_A  (BM * LDA_B)             // 3072
#define FP_STG (FP_A + BK * LDB_B)     // 11520
#define NS 2
#define SMEM_TOTAL (NS * FP_STG)       // 23040 -> 2 CTA/SM

__device__ int g_starts[G_];

__global__ void starts_kernel(const int* __restrict__ counts) {
    if (threadIdx.x == 0 && blockIdx.x == 0) {
        int s = 0;
        for (int g = 0; g < G_; ++g) { g_starts[g] = s; s += counts[g]; }
    }
}

static __device__ __forceinline__ uint32_t smem_u32(const void* p) {
    uint32_t a;
    asm("{ .reg .u64 t; cvta.to.shared.u64 t, %1; cvt.u32.u64 %0, t; }" : "=r"(a) : "l"(p));
    return a;
}
static __device__ __forceinline__ uint32_t pack_h2(float lo, float hi) {
    uint32_t d;
    asm("cvt.rn.f16x2.f32 %0, %1, %2;" : "=r"(d) : "f"(hi), "f"(lo));
    return d;
}
static __device__ __forceinline__ float4 ldg_cg(const float* p) {
    float4 v;
    asm volatile("ld.global.cg.v4.f32 {%0,%1,%2,%3}, [%4];"
                 : "=f"(v.x), "=f"(v.y), "=f"(v.z), "=f"(v.w) : "l"(p));
    return v;
}
static __device__ __forceinline__ void sts64(uint32_t addr, uint32_t w0, uint32_t w1) {
    asm volatile("st.shared.v2.b32 [%0], {%1, %2};" :: "r"(addr), "r"(w0), "r"(w1));
}

#define LDSM4(r, a) \
    asm volatile("ldmatrix.sync.aligned.m8n8.x4.shared.b16 {%0,%1,%2,%3}, [%4];" \
        : "=r"((r)[0]), "=r"((r)[1]), "=r"((r)[2]), "=r"((r)[3]) : "r"(a))
#define LDSM4T(r, a) \
    asm volatile("ldmatrix.sync.aligned.m8n8.x4.trans.shared.b16 {%0,%1,%2,%3}, [%4];" \
        : "=r"((r)[0]), "=r"((r)[1]), "=r"((r)[2]), "=r"((r)[3]) : "r"(a))

static __device__ __forceinline__ void mma_f16(float* c, const uint32_t* a,
                                               uint32_t b0, uint32_t b1) {
    asm volatile(
        "mma.sync.aligned.m16n8k16.row.col.f32.f16.f16.f32 "
        "{%0,%1,%2,%3}, {%4,%5,%6,%7}, {%8,%9}, {%0,%1,%2,%3};\n"
        : "+f"(c[0]), "+f"(c[1]), "+f"(c[2]), "+f"(c[3])
        : "r"(a[0]), "r"(a[1]), "r"(a[2]), "r"(a[3]), "r"(b0), "r"(b1));
}

__global__ __launch_bounds__(256, 2)
void grouped_gemm_kernel(const float* __restrict__ X, const float* __restrict__ W,
                         const int* __restrict__ counts, float* __restrict__ Y) {
    extern __shared__ char smem[];

    const int g  = blockIdx.z;
    const int mt = blockIdx.y;
    const int nt = blockIdx.x;
    const int cnt = counts[g];
    if (mt * BM >= cnt) return;
    const int gstart = g_starts[g];

    const int t    = threadIdx.x;
    const int lane = t & 31;
    const int wid  = t >> 5;
    const int m0 = (wid & 1) * 32;
    const int n0 = (wid >> 1) * 64;
    const int tg  = lane >> 2;
    const int tig = lane & 3;
    const uint32_t sBase = smem_u32(smem);

    // ---- global load mapping ----
    // A: 1 float4/thread: row = t>>2 (0..63), kv = t&3
    const int a_row = t >> 2;
    const int a_kv  = t & 3;
    long long arow = (long long)gstart + mt * BM + a_row;
    if (arow > T_ - 1) arow = T_ - 1;    // clamp; masked in epilogue
    const float* Ag = X + arow * DIN_ + a_kv * 4;
    const uint32_t aFp = (uint32_t)(a_row * LDA_B + a_kv * 8);

    // B: 4 float4/thread: k = (t>>6) + 4*i, nv = t&63
    const int b_k0 = t >> 6;             // 0..3
    const int b_nv = t & 63;
    int bcol = nt * BN + b_nv * 4;
    if (bcol > DOUT_ - 4) bcol = DOUT_ - 4;   // clamp tail tile
    const float* Bg = W + (long long)g * DIN_ * DOUT_ + bcol;
    const uint32_t bFp = (uint32_t)(b_k0 * LDB_B + b_nv * 8);

    // ---- 2-slot register staging (use-distance = 2 iterations) ----
    float4 rA[2], rB[2][4];
    auto load_g = [&](int kt, int slot) {
        const int k0 = kt * BK;
        rA[slot] = ldg_cg(Ag + k0);
        #pragma unroll
        for (int i = 0; i < 4; ++i)
            rB[slot][i] = ldg_cg(Bg + (long long)(k0 + b_k0 + 4 * i) * DOUT_);
    };
    auto store_s = [&](int kt, int slot) {
        const uint32_t fp = sBase + (uint32_t)((kt & (NS - 1)) * FP_STG);
        sts64(fp + aFp, pack_h2(rA[slot].x, rA[slot].y), pack_h2(rA[slot].z, rA[slot].w));
        #pragma unroll
        for (int i = 0; i < 4; ++i)
            sts64(fp + FP_A + bFp + (uint32_t)(4 * i * LDB_B),
                  pack_h2(rB[slot][i].x, rB[slot][i].y),
                  pack_h2(rB[slot][i].z, rB[slot][i].w));
    };

    // ---- ldmatrix addresses ----
    const int l15 = lane & 15;
    const int lhi = lane >> 4;
    uint32_t aoff[2];
    #pragma unroll
    for (int mf = 0; mf < 2; ++mf)
        aoff[mf] = (uint32_t)((m0 + mf * 16 + l15) * LDA_B + lhi * 16);
    uint32_t boff[4];
    #pragma unroll
    for (int p = 0; p < 4; ++p)
        boff[p] = (uint32_t)(FP_A + l15 * LDB_B + (n0 + p * 16 + lhi * 8) * 2);

    float acc[2][8][4];
    #pragma unroll
    for (int mf = 0; mf < 2; ++mf)
        #pragma unroll
        for (int nf = 0; nf < 8; ++nf)
            #pragma unroll
            for (int i = 0; i < 4; ++i) acc[mf][nf][i] = 0.0f;

    // prologue: regs hold stages 0,1; store stage 0; refill slot0 with stage 2
    load_g(0, 0);
    load_g(1, 1);
    store_s(0, 0);
    load_g(2, 0);
    __syncthreads();

    #pragma unroll 2
    for (int kt = 0; kt < NK; ++kt) {
        const uint32_t fp = sBase + (uint32_t)((kt & (NS - 1)) * FP_STG);

        // fragments for stage kt (buffer synced last iteration)
        uint32_t af[2][4], bf[4][4];
        LDSM4(af[0], fp + aoff[0]);
        LDSM4(af[1], fp + aoff[1]);
        #pragma unroll
        for (int p = 0; p < 4; ++p)
            LDSM4T(bf[p], fp + boff[p]);

        // stage kt+1: regs (loaded at iter kt-1 or prologue) -> smem
        if (kt + 1 < NK) store_s(kt + 1, (kt + 1) & 1);
        // refill freed reg slot with stage kt+3 (consumed at iter kt+2)
        if (kt + 3 < NK) load_g(kt + 3, (kt + 1) & 1);

        #pragma unroll
        for (int p = 0; p < 4; ++p)
            #pragma unroll
            for (int mf = 0; mf < 2; ++mf) {
                mma_f16(acc[mf][2 * p],     af[mf], bf[p][0], bf[p][1]);
                mma_f16(acc[mf][2 * p + 1], af[mf], bf[p][2], bf[p][3]);
            }

        __syncthreads();                 // stage kt+1 visible; stage kt readers done
    }

    // ---- epilogue: predicated float2 stores ----
    #pragma unroll
    for (int mf = 0; mf < 2; ++mf) {
        const int r0 = mt * BM + m0 + mf * 16 + tg;
        const int r1 = r0 + 8;
        #pragma unroll
        for (int nf = 0; nf < 8; ++nf) {
            const int col = nt * BN + n0 + nf * 8 + tig * 2;
            if (col < DOUT_) {
                if (r0 < cnt) {
                    float2 v = make_float2(acc[mf][nf][0], acc[mf][nf][1]);
                    *(float2*)&Y[(long long)(gstart + r0) * DOUT_ + col] = v;
                }
                if (r1 < cnt) {
                    float2 v = make_float2(acc[mf][nf][2], acc[mf][nf][3]);
                    *(float2*)&Y[(long long)(gstart + r1) * DOUT_ + col] = v;
                }
            }
        }
    }
}

extern "C" void kernel_launch(void* const* d_in, const int* in_sizes, int n_in,
                              void* d_out, int out_size) {
    const float* x    = (const float*)d_in[0];
    const float* w    = (const float*)d_in[1];
    const int*   cnts = (const int*)d_in[2];
    float* y = (float*)d_out;

    starts_kernel<<<1, 32>>>(cnts);

    cudaFuncSetAttribute(grouped_gemm_kernel,
                         cudaFuncAttributeMaxDynamicSharedMemorySize, SMEM_TOTAL);
    dim3 grid(NT_N, CAP_ / BM, G_);      // (7, 4, 64)
    grouped_gemm_kernel<<<grid, 256, SMEM_TOTAL>>>(x, w, cnts, y);
}

// round 16
// speedup vs baseline: 1.8394x; 1.8394x over previous
#include <cuda_runtime.h>
#include <cstdint>

// ---------------- problem constants ----------------
#define G_    64
#define T_    8192
#define DIN_  2560
#define DOUT_ 1664
#define CAP_  256

// ---------------- tiling ----------------
#define BM 64
#define BN 256
#define BK 16
#define NK (DIN_ / BK)                 // 160
#define NT_N ((DOUT_ + BN - 1) / BN)   // 7 (last tile masked)

// raw f32 staging ring
#define RAW_A   (BM * BK * 4)          // 4096
#define RAW_B   (BK * BN * 4)          // 16384
#define RAW_STG (RAW_A + RAW_B)        // 20480
#define RS      3

// fp16 compute ring
#define LDA_B 48                       // A fp16 row stride (32 data + 16 pad)
#define LDB_B 528                      // B fp16 row stride (512 data + 16 pad)
#define FP_A  (BM * LDA_B)             // 3072
#define FP_STG (FP_A + BK * LDB_B)     // 11520
#define FS    4

#define SM_FP (RS * RAW_STG)                      // 61440
#define SMEM_TOTAL (SM_FP + FS * FP_STG)          // 107520 -> 2 CTA/SM

__device__ int g_starts[G_];

__global__ void starts_kernel(const int* __restrict__ counts) {
    if (threadIdx.x == 0 && blockIdx.x == 0) {
        int s = 0;
        for (int g = 0; g < G_; ++g) { g_starts[g] = s; s += counts[g]; }
    }
}

static __device__ __forceinline__ uint32_t smem_u32(const void* p) {
    uint32_t a;
    asm("{ .reg .u64 t; cvta.to.shared.u64 t, %1; cvt.u32.u64 %0, t; }" : "=r"(a) : "l"(p));
    return a;
}
static __device__ __forceinline__ uint32_t pack_h2(float lo, float hi) {
    uint32_t d;
    asm("cvt.rn.f16x2.f32 %0, %1, %2;" : "=r"(d) : "f"(hi), "f"(lo));
    return d;
}
static __device__ __forceinline__ void cp16(uint32_t dst, const void* src) {
    asm volatile("cp.async.cg.shared.global [%0], [%1], 16;" :: "r"(dst), "l"(src));
}
#define CP_COMMIT()   asm volatile("cp.async.commit_group;")
#define CP_WAIT(n)    asm volatile("cp.async.wait_group %0;" :: "n"(n) : "memory")

static __device__ __forceinline__ float4 lds128(uint32_t addr) {
    float4 v;
    asm volatile("ld.shared.v4.f32 {%0,%1,%2,%3}, [%4];"
                 : "=f"(v.x), "=f"(v.y), "=f"(v.z), "=f"(v.w) : "r"(addr));
    return v;
}
static __device__ __forceinline__ void sts64(uint32_t addr, uint32_t w0, uint32_t w1) {
    asm volatile("st.shared.v2.b32 [%0], {%1, %2};" :: "r"(addr), "r"(w0), "r"(w1));
}

#define LDSM4(r, a) \
    asm volatile("ldmatrix.sync.aligned.m8n8.x4.shared.b16 {%0,%1,%2,%3}, [%4];" \
        : "=r"((r)[0]), "=r"((r)[1]), "=r"((r)[2]), "=r"((r)[3]) : "r"(a))
#define LDSM4T(r, a) \
    asm volatile("ldmatrix.sync.aligned.m8n8.x4.trans.shared.b16 {%0,%1,%2,%3}, [%4];" \
        : "=r"((r)[0]), "=r"((r)[1]), "=r"((r)[2]), "=r"((r)[3]) : "r"(a))

static __device__ __forceinline__ void mma_f16(float* c, const uint32_t* a,
                                               uint32_t b0, uint32_t b1) {
    asm volatile(
        "mma.sync.aligned.m16n8k16.row.col.f32.f16.f16.f32 "
        "{%0,%1,%2,%3}, {%4,%5,%6,%7}, {%8,%9}, {%0,%1,%2,%3};\n"
        : "+f"(c[0]), "+f"(c[1]), "+f"(c[2]), "+f"(c[3])
        : "r"(a[0]), "r"(a[1]), "r"(a[2]), "r"(a[3]), "r"(b0), "r"(b1));
}

__global__ __launch_bounds__(256, 2)
void grouped_gemm_kernel(const float* __restrict__ X, const float* __restrict__ W,
                         const int* __restrict__ counts, float* __restrict__ Y) {
    extern __shared__ char smem[];       // [3 raw f32 stages][4 fp16 stages]

    const int g  = blockIdx.z;
    const int mt = blockIdx.y;
    const int nt = blockIdx.x;
    const int cnt = counts[g];
    if (mt * BM >= cnt) return;
    const int gstart = g_starts[g];

    const int t    = threadIdx.x;
    const int lane = t & 31;
    const int wid  = t >> 5;
    const int m0 = (wid & 1) * 32;
    const int n0 = (wid >> 1) * 64;
    const int tg  = lane >> 2;
    const int tig = lane & 3;

    // ---- cp.async mapping (f32 raw) ----
    const int a_row = t >> 2;            // 0..63
    const int a_kv  = t & 3;
    long long arow = (long long)gstart + mt * BM + a_row;
    if (arow > T_ - 1) arow = T_ - 1;    // clamp; masked in epilogue
    const float* Ag = X + arow * DIN_ + a_kv * 4;
    const uint32_t aRawOff = (uint32_t)(a_row * 64 + a_kv * 16);

    const int b_k0 = t >> 6;             // 0..3
    const int b_nv = t & 63;
    int bcol = nt * BN + b_nv * 4;
    if (bcol > DOUT_ - 4) bcol = DOUT_ - 4;   // clamp tail tile
    const float* Bg = W + (long long)g * DIN_ * DOUT_ + bcol;
    const uint32_t bRawOff = (uint32_t)(b_k0 * 1024 + b_nv * 16);

    const uint32_t sBase  = smem_u32(smem);
    const uint32_t fpBase = sBase + SM_FP;

    auto issue_stage = [&](int kt) {
        const uint32_t stg = sBase + (uint32_t)((kt % RS) * RAW_STG);
        const int k0 = kt * BK;
        cp16(stg + aRawOff, Ag + k0);
        #pragma unroll
        for (int i = 0; i < 4; ++i)
            cp16(stg + RAW_A + bRawOff + (uint32_t)(4 * i * 1024),
                 Bg + (long long)(k0 + b_k0 + 4 * i) * DOUT_);
    };

    const uint32_t aFpOff = (uint32_t)(a_row * LDA_B + a_kv * 8);
    const uint32_t bFpOff = (uint32_t)(b_k0 * LDB_B + b_nv * 8);
    auto convert_stage = [&](int kt) {   // thread-private: reads own cp'd bytes
        const uint32_t raw = sBase + (uint32_t)((kt % RS) * RAW_STG);
        const uint32_t fp  = fpBase + (uint32_t)((kt & (FS - 1)) * FP_STG);
        float4 v = lds128(raw + aRawOff);
        sts64(fp + aFpOff, pack_h2(v.x, v.y), pack_h2(v.z, v.w));
        #pragma unroll
        for (int i = 0; i < 4; ++i) {
            float4 b = lds128(raw + RAW_A + bRawOff + (uint32_t)(4 * i * 1024));
            sts64(fp + FP_A + bFpOff + (uint32_t)(4 * i * LDB_B),
                  pack_h2(b.x, b.y), pack_h2(b.z, b.w));
        }
    };

    // ---- ldmatrix addresses (within one fp16 stage) ----
    const int l15 = lane & 15;
    const int lhi = lane >> 4;
    uint32_t aoff[2];
    #pragma unroll
    for (int mf = 0; mf < 2; ++mf)
        aoff[mf] = (uint32_t)((m0 + mf * 16 + l15) * LDA_B + lhi * 16);
    uint32_t boff[4];
    #pragma unroll
    for (int p = 0; p < 4; ++p)
        boff[p] = (uint32_t)(FP_A + l15 * LDB_B + (n0 + p * 16 + lhi * 8) * 2);

    float acc[2][8][4];
    #pragma unroll
    for (int mf = 0; mf < 2; ++mf)
        #pragma unroll
        for (int nf = 0; nf < 8; ++nf)
            #pragma unroll
            for (int i = 0; i < 4; ++i) acc[mf][nf][i] = 0.0f;

    auto compute_stage = [&](int kt) {
        const uint32_t fp = fpBase + (uint32_t)((kt & (FS - 1)) * FP_STG);
        uint32_t af[2][4], bf[4][4];
        LDSM4(af[0], fp + aoff[0]);
        LDSM4(af[1], fp + aoff[1]);
        #pragma unroll
        for (int p = 0; p < 4; ++p)
            LDSM4T(bf[p], fp + boff[p]);
        #pragma unroll
        for (int p = 0; p < 4; ++p)
            #pragma unroll
            for (int mf = 0; mf < 2; ++mf) {
                mma_f16(acc[mf][2 * p],     af[mf], bf[p][0], bf[p][1]);
                mma_f16(acc[mf][2 * p + 1], af[mf], bf[p][2], bf[p][3]);
            }
    };

    // ---- prologue ----
    issue_stage(0); CP_COMMIT();
    issue_stage(1); CP_COMMIT();
    issue_stage(2); CP_COMMIT();
    CP_WAIT(1);                          // stages 0,1 resident
    convert_stage(0);                    // raw slots 0,1 freed (thread-private)
    convert_stage(1);
    issue_stage(3); CP_COMMIT();         // -> raw slot 0
    __syncthreads();                     // fp 0,1 visible

    // ---- main loop: 2 stages per sync period ----
    for (int j = 0; j < NK / 2; ++j) {
        const int k0 = 2 * j;

        CP_WAIT(0);                      // raw k0+2, k0+3 resident
        // (sync was done at end of prev iter / prologue)

        // convert next two stages (raw reads are thread-private; fp slots
        // (k0+2)&3,(k0+3)&3 are disjoint from compute slots k0&3,(k0+1)&3)
        if (k0 + 2 < NK) convert_stage(k0 + 2);
        if (k0 + 3 < NK) convert_stage(k0 + 3);

        // refill raw ring: k0+4 -> slot (k0+1)%3 (freed last iter),
        //                  k0+5 -> slot (k0+2)%3 (freed just above)
        if (k0 + 4 < NK) issue_stage(k0 + 4);
        CP_COMMIT();
        if (k0 + 5 < NK) issue_stage(k0 + 5);
        CP_COMMIT();

        compute_stage(k0);
        compute_stage(k0 + 1);

        __syncthreads();                 // converts of k0+2,k0+3 visible; LDSM of k0,k0+1 done
    }

    // ---- epilogue: predicated float2 stores ----
    #pragma unroll
    for (int mf = 0; mf < 2; ++mf) {
        const int r0 = mt * BM + m0 + mf * 16 + tg;
        const int r1 = r0 + 8;
        #pragma unroll
        for (int nf = 0; nf < 8; ++nf) {
            const int col = nt * BN + n0 + nf * 8 + tig * 2;
            if (col < DOUT_) {
                if (r0 < cnt) {
                    float2 v = make_float2(acc[mf][nf][0], acc[mf][nf][1]);
                    *(float2*)&Y[(long long)(gstart + r0) * DOUT_ + col] = v;
                }
                if (r1 < cnt) {
                    float2 v = make_float2(acc[mf][nf][2], acc[mf][nf][3]);
                    *(float2*)&Y[(long long)(gstart + r1) * DOUT_ + col] = v;
                }
            }
        }
    }
}

extern "C" void kernel_launch(void* const* d_in, const int* in_sizes, int n_in,
                              void* d_out, int out_size) {
    const float* x    = (const float*)d_in[0];
    const float* w    = (const float*)d_in[1];
    const int*   cnts = (const int*)d_in[2];
    float* y = (float*)d_out;

    starts_kernel<<<1, 32>>>(cnts);

    cudaFuncSetAttribute(grouped_gemm_kernel,
                         cudaFuncAttributeMaxDynamicSharedMemorySize, SMEM_TOTAL);
    dim3 grid(NT_N, CAP_ / BM, G_);      // (7, 4, 64)
    grouped_gemm_kernel<<<grid, 256, SMEM_TOTAL>>>(x, w, cnts, y);
}